// round 9
// baseline (speedup 1.0000x reference)
#include <cuda_runtime.h>
#include <cstdint>

#define BATCH 1024
#define NUM_CLS 58

// ---------------- device scratch (no allocations allowed) ----------------
__device__ uint4   g_pw1q[9 * 128];       // packed w1 signs, layout [tap][oc] -> uint4 of words 0..3
__device__ unsigned g_pw2[9 * 4 * 128];   // layout [tap][word][oc]
__device__ unsigned g_pw3[9 * 4 * 128];
__device__ unsigned g_pw4[4 * 128];       // layout [word][oc]

// ---------------- weight sign packing (warp-ballot, coalesced) ----------------
__global__ void pack_weights_kernel(const float* __restrict__ w1, const float* __restrict__ w2,
                                    const float* __restrict__ w3, const float* __restrict__ w4) {
    int gw   = (blockIdx.x * blockDim.x + threadIdx.x) >> 5;
    int lane = threadIdx.x & 31;
    if (gw >= 2048) return;
    int t  = gw >> 9;
    int r  = gw & 511;
    int oc = r >> 2;
    int wi = r & 3;
    if (t < 3) {
        const float* w = (t == 0) ? w1 : ((t == 1) ? w2 : w3);
        const float* p = w + ((size_t)(oc * 128 + wi * 32 + lane)) * 9;
        float v[9];
#pragma unroll
        for (int k = 0; k < 9; k++) v[k] = p[k];
        unsigned myword = 0;
#pragma unroll
        for (int tap = 0; tap < 9; tap++) {
            unsigned wd = __ballot_sync(0xffffffffu, v[tap] >= 0.0f);
            if (lane == tap) myword = wd;
        }
        if (lane < 9) {
            if (t == 0) {
                // uint4-friendly layout: [tap][oc] -> 4 words
                ((unsigned*)g_pw1q)[(lane * 128 + oc) * 4 + wi] = myword;
            } else {
                unsigned* pw = (t == 1) ? g_pw2 : g_pw3;
                pw[(lane * 4 + wi) * 128 + oc] = myword;
            }
        }
    } else {
        float v = w4[oc * 128 + wi * 32 + lane];
        unsigned wd = __ballot_sync(0xffffffffu, v >= 0.0f);
        if (lane == 0) g_pw4[wi * 128 + oc] = wd;
    }
}

// ---- phase-0 helper: PIX pooled pixels sharing 12-col row loads ----
// Per-candidate accumulation order is (c asc, ky asc, kx asc) — identical to prior rounds.
template<int PIX>
__device__ __forceinline__ void conv_group(const float* __restrict__ xs, int y0, int x0c,
                                           const float* __restrict__ wr, int cg,
                                           unsigned* __restrict__ a1w, int pbase, int lane) {
    constexpr int NW = (PIX == 4) ? 3 : 2;    // float4 loads per row
    float acc[PIX][4];
#pragma unroll
    for (int pi = 0; pi < PIX; pi++) {
        acc[pi][0] = 0.f; acc[pi][1] = 0.f; acc[pi][2] = 0.f; acc[pi][3] = 0.f;
    }
#pragma unroll
    for (int c = 0; c < 3; c++) {
#pragma unroll
        for (int dy = 0; dy < 4; dy++) {
            float e[NW * 4];
            const float4* r4 = (const float4*)&xs[c * 1024 + (y0 + dy) * 32 + x0c];
#pragma unroll
            for (int j = 0; j < NW; j++) {
                float4 q = r4[j];
                e[j * 4 + 0] = q.x; e[j * 4 + 1] = q.y; e[j * 4 + 2] = q.z; e[j * 4 + 3] = q.w;
            }
#pragma unroll
            for (int kx = 0; kx < 3; kx++) {
                if (dy <= 2) {
                    float w = wr[c * 9 + dy * 3 + kx];
#pragma unroll
                    for (int pi = 0; pi < PIX; pi++) {
                        acc[pi][0] += e[2 * pi + kx] * w;
                        acc[pi][1] += e[2 * pi + 1 + kx] * w;
                    }
                }
                if (dy >= 1) {
                    float w = wr[c * 9 + (dy - 1) * 3 + kx];
#pragma unroll
                    for (int pi = 0; pi < PIX; pi++) {
                        acc[pi][2] += e[2 * pi + kx] * w;
                        acc[pi][3] += e[2 * pi + 1 + kx] * w;
                    }
                }
            }
        }
    }
#pragma unroll
    for (int pi = 0; pi < PIX; pi++) {
        float best = fmaxf(fmaxf(acc[pi][0], acc[pi][1]), fmaxf(acc[pi][2], acc[pi][3]));
        unsigned word = __ballot_sync(0xffffffffu, best >= 0.0f);
        if (lane == 0) a1w[(pbase + pi) * 4 + cg] = word;
    }
}

// ---- binconv1 for 3 consecutive pixel indices q0..q0+2 (row-major over 6x6) ----
// Weights loaded per call via __ldcv (volatile: blocks hoisting, keeps regs transient).
__device__ __forceinline__ void binconv1_pixels(int q0, const uint4* __restrict__ a1s,
                                                unsigned* __restrict__ a2w,
                                                int oc, int cg, int lane) {
    uint4 wv[9];
#pragma unroll
    for (int tap = 0; tap < 9; tap++) wv[tap] = __ldcv(&g_pw1q[tap * 128 + oc]);

#pragma unroll
    for (int j = 0; j < 3; j++) {
        int q  = q0 + j;
        int pr = q / 6, px = q - pr * 6;
        int y0 = 2 * pr, x0 = 2 * px;

        int smin = 1 << 30;
#pragma unroll
        for (int cy = 0; cy < 2; cy++)
#pragma unroll
            for (int cx = 0; cx < 2; cx++) {
                int s = 0;
#pragma unroll
                for (int ky = 0; ky < 3; ky++)
#pragma unroll
                    for (int kx = 0; kx < 3; kx++) {
                        uint4 xv = a1s[(y0 + cy + ky) * 15 + (x0 + cx + kx)];
                        uint4 wq = wv[ky * 3 + kx];
                        s += __popc(xv.x ^ wq.x) + __popc(xv.y ^ wq.y) +
                             __popc(xv.z ^ wq.z) + __popc(xv.w ^ wq.w);
                    }
                smin = min(smin, s);
            }
        // dot = 1152 - 2*smin ; sign bit = (dot >= 0)
        unsigned word = __ballot_sync(0xffffffffu, smin <= 576);
        if (lane == 0) a2w[q * 4 + cg] = word;
    }
}

// ---------------- single merged model kernel: block = image, 128 threads (4 warps) ----------------
// Phase 0 (conv0, FMA-pipe) and phase 1 (binconv1, ALU-pipe) are software-pipelined by rows:
// after conv row py>=3, 3 binconv1 pixels interleave per iteration (deps: pixel q needs
// a1 rows <= 2*(q/6)+3 <= py — verified for the schedule q = 3*(py-3)+j, py=3..14).
__global__ __launch_bounds__(128, 7) void model_kernel(const float* __restrict__ x,
                                                       const float* __restrict__ w0,
                                                       const float* __restrict__ w5,
                                                       float* __restrict__ out) {
    __shared__ float xs[3 * 32 * 32];
    __shared__ uint4 a1s[225];
    __shared__ uint4 a2v[36];
    __shared__ uint4 a3v[9];
    __shared__ unsigned s4w[4];
    __shared__ float rs[128];
    __shared__ float lg[NUM_CLS];

    int b    = blockIdx.x;
    int tid  = threadIdx.x;
    int warp = tid >> 5;
    int lane = tid & 31;

    // ---- load image ----
    const float4* xb4 = (const float4*)(x + (size_t)b * 3072);
    float4* xs4 = (float4*)xs;
    for (int i = tid; i < 768; i += 128) xs4[i] = xb4[i];
    __syncthreads();

    int cg = warp;
    int oc = cg * 32 + lane;

    // ---- interleaved phase 0 + phase 1 ----
    {
        float wr[27];
#pragma unroll
        for (int k = 0; k < 27; k++) wr[k] = w0[oc * 27 + k];

        unsigned* a1w = (unsigned*)a1s;
        unsigned* a2w = (unsigned*)a2v;

        for (int py = 0; py < 15; py++) {
            int y0 = 2 * py;
            int pb = py * 15;
            conv_group<4>(xs, y0, 0,  wr, cg, a1w, pb + 0,  lane);
            conv_group<4>(xs, y0, 8,  wr, cg, a1w, pb + 4,  lane);
            conv_group<4>(xs, y0, 16, wr, cg, a1w, pb + 8,  lane);
            conv_group<3>(xs, y0, 24, wr, cg, a1w, pb + 12, lane);
            if (py >= 3) {
                __syncthreads();   // a1 rows <= py now visible block-wide
                binconv1_pixels(3 * (py - 3), a1s, a2w, oc, cg, lane);
            }
        }
    }
    __syncthreads();

    // ---- phase 2: binconv2 (4 warps: cg = warp, 9 pixels each) ----
    {
        uint4 wr[9];
#pragma unroll
        for (int tap = 0; tap < 9; tap++) {
            wr[tap].x = g_pw2[(tap * 4 + 0) * 128 + oc];
            wr[tap].y = g_pw2[(tap * 4 + 1) * 128 + oc];
            wr[tap].z = g_pw2[(tap * 4 + 2) * 128 + oc];
            wr[tap].w = g_pw2[(tap * 4 + 3) * 128 + oc];
        }

        for (int p = 0; p < 9; p++) {
            int py = p / 3, px = p - py * 3;

            int smin = 1 << 30;
#pragma unroll
            for (int cy = 0; cy < 2; cy++)
#pragma unroll
                for (int cx = 0; cx < 2; cx++) {
                    int s = 0;
#pragma unroll
                    for (int ky = 0; ky < 3; ky++)
#pragma unroll
                        for (int kx = 0; kx < 3; kx++) {
                            uint4 xv = a2v[(py + cy + ky) * 6 + (px + cx + kx)];
                            uint4 wv = wr[ky * 3 + kx];
                            s += __popc(xv.x ^ wv.x) + __popc(xv.y ^ wv.y) +
                                 __popc(xv.z ^ wv.z) + __popc(xv.w ^ wv.w);
                        }
                    smin = min(smin, s);
                }
            unsigned word = __ballot_sync(0xffffffffu, smin <= 576);
            if (lane == 0) ((unsigned*)a3v)[p * 4 + cg] = word;
        }
    }
    __syncthreads();

    // ---- phase 3: head (128 threads = output channel) ----
    {
        int s = 0;
#pragma unroll
        for (int tap = 0; tap < 9; tap++) {
            uint4 xv = a3v[tap];
            s += __popc(xv.x ^ g_pw3[(tap * 4 + 0) * 128 + tid]);
            s += __popc(xv.y ^ g_pw3[(tap * 4 + 1) * 128 + tid]);
            s += __popc(xv.z ^ g_pw3[(tap * 4 + 2) * 128 + tid]);
            s += __popc(xv.w ^ g_pw3[(tap * 4 + 3) * 128 + tid]);
        }
        unsigned word = __ballot_sync(0xffffffffu, s <= 576);  // sign(1152 - 2s)
        if (lane == 0) s4w[warp] = word;
    }
    __syncthreads();

    {
        int t = 0;
#pragma unroll
        for (int wi = 0; wi < 4; wi++) t += __popc(s4w[wi] ^ g_pw4[wi * 128 + tid]);
        rs[tid] = fmaxf((float)(128 - 2 * t), 0.0f);
    }
    __syncthreads();

    // fp32 1x1 conv to NUM_CLS logits
    if (tid < NUM_CLS) {
        float acc = 0.0f;
#pragma unroll 8
        for (int o = 0; o < 128; o++) acc += w5[tid * 128 + o] * rs[o];
        lg[tid] = acc;
    }
    __syncthreads();

    // softmax over NUM_CLS
    if (tid < NUM_CLS) {
        float m = -3.4e38f;
        for (int j = 0; j < NUM_CLS; j++) m = fmaxf(m, lg[j]);
        float den = 0.0f;
        for (int j = 0; j < NUM_CLS; j++) den += expf(lg[j] - m);
        out[(size_t)b * NUM_CLS + tid] = expf(lg[tid] - m) / den;
    }
}

// ---------------- launch ----------------
extern "C" void kernel_launch(void* const* d_in, const int* in_sizes, int n_in,
                              void* d_out, int out_size) {
    const float* x  = (const float*)d_in[0];
    const float* w0 = (const float*)d_in[1];
    const float* w1 = (const float*)d_in[2];
    const float* w2 = (const float*)d_in[3];
    const float* w3 = (const float*)d_in[4];
    const float* w4 = (const float*)d_in[5];
    const float* w5 = (const float*)d_in[6];
    float* out = (float*)d_out;

    pack_weights_kernel<<<256, 256>>>(w1, w2, w3, w4);
    model_kernel<<<BATCH, 128>>>(x, w0, w5, out);
}